// round 7
// baseline (speedup 1.0000x reference)
#include <cuda_runtime.h>
#include <math.h>
#include <stdint.h>

#define TT 512
#define CC 128
#define HH 512
#define ROWS 1024
#define CH 16      // k-chunk

// ---------------- globals (cross-kernel intermediates) ----------------
__device__ float g_v[ROWS*CC];
__device__ float g_k[ROWS*CC];
__device__ float g_r[ROWS*CC];

// ---------------- helpers ----------------
__device__ __forceinline__ float wsum(float x) {
    #pragma unroll
    for (int o = 16; o; o >>= 1) x += __shfl_xor_sync(0xffffffffu, x, o);
    return x;
}
__device__ __forceinline__ float rcpa(float x) {
    float r; asm("rcp.approx.f32 %0, %1;" : "=f"(r) : "f"(x)); return r;
}
typedef unsigned long long ull;
__device__ __forceinline__ ull pack2(float x, float y) {
    ull r; asm("mov.b64 %0, {%1, %2};" : "=l"(r) : "f"(x), "f"(y)); return r;
}
__device__ __forceinline__ void unpack2(ull p, float& x, float& y) {
    asm("mov.b64 {%0, %1}, %2;" : "=f"(x), "=f"(y) : "l"(p));
}
__device__ __forceinline__ ull fma2(ull a, ull b, ull c) {
    ull d; asm("fma.rn.f32x2 %0, %1, %2, %3;" : "=l"(d) : "l"(a), "l"(b), "l"(c)); return d;
}
__device__ __forceinline__ ull mul2(ull a, ull b) {
    ull d; asm("mul.rn.f32x2 %0, %1, %2;" : "=l"(d) : "l"(a), "l"(b)); return d;
}
__device__ __forceinline__ ull add2(ull a, ull b) {
    ull d; asm("add.rn.f32x2 %0, %1, %2;" : "=l"(d) : "l"(a), "l"(b)); return d;
}
__device__ __forceinline__ void cpasync16(uint32_t saddr, const void* g) {
    asm volatile("cp.async.ca.shared.global [%0], [%1], 16;" :: "r"(saddr), "l"(g));
}
__device__ __forceinline__ void cpcommit() { asm volatile("cp.async.commit_group;"); }
template<int N> __device__ __forceinline__ void cpwait() {
    asm volatile("cp.async.wait_group %0;" :: "n"(N));
}

// ---------------- GEMM scratch ----------------
struct __align__(16) SmemGemm {
    float Bs[2][CH][CC];     // 16 KB (aliased as 4x[8][128] split-K reduce buf)
    ull   AsD[2][CH][8];     //  2 KB (pre-duplicated f32x2 A)
};

// GEMM: 8 rows x 128 cols, 256 thr (8 warps), 8-way split-K over 16-k chunks.
// Asrc points at an 8-row tile in shared memory, row stride lda (pad -> conflict-free).
// Result: thread (warp w = row, lane = 4 cols) gets outv[4].
template<int K>
__device__ __forceinline__ void gemm_sm(SmemGemm& sg, const float* __restrict__ Asrc, int lda,
                                        const float* __restrict__ W, int ldw, int bn,
                                        float (&outv)[4]) {
    const int tid = threadIdx.x, w = tid >> 5, lane = tid & 31;
    constexpr int NC = K / CH;
    uint32_t bs_base = (uint32_t)__cvta_generic_to_shared(&sg.Bs[0][0][0]);
    const int ak = tid >> 3, ar = tid & 7;      // valid when tid < 128

    __syncthreads();   // protect sg + A-tile from prior stage users

    #define STAGE_B(c, buf) do {                                                 \
        const float* _src = W + (size_t)((c)*CH)*ldw + bn;                       \
        _Pragma("unroll")                                                        \
        for (int _j = 0; _j < 2; _j++) {                                         \
            int _idx = tid + _j*256;                                             \
            int _kk = _idx >> 5, _q = _idx & 31;                                 \
            cpasync16(bs_base + (uint32_t)(((buf)*CH + _kk)*CC + (_q<<2))*4u,    \
                      _src + (size_t)_kk*ldw + (_q<<2));                         \
        }                                                                        \
        cpcommit();                                                              \
    } while (0)

    STAGE_B(0, 0);
    if (tid < 128) {
        float aCur = Asrc[ar*lda + ak];
        sg.AsD[0][ak][ar] = pack2(aCur, aCur);
    }

    ull acc[8][2];
    #pragma unroll
    for (int r = 0; r < 8; r++) { acc[r][0] = 0ull; acc[r][1] = 0ull; }

    #pragma unroll 1
    for (int c = 0; c < NC; c++) {
        float aNext = 0.f;
        if (c + 1 < NC) {
            STAGE_B(c+1, (c+1)&1);
            if (tid < 128) aNext = Asrc[ar*lda + (c+1)*CH + ak];
            cpwait<1>();
        } else {
            cpwait<0>();
        }
        __syncthreads();
        const int buf = c & 1;
        #pragma unroll
        for (int j = 0; j < CH/8; j++) {
            const int kk = w*(CH/8) + j;
            const ull* ad = &sg.AsD[buf][kk][0];
            ulonglong2 a01 = *(const ulonglong2*)(ad);
            ulonglong2 a23 = *(const ulonglong2*)(ad + 2);
            ulonglong2 a45 = *(const ulonglong2*)(ad + 4);
            ulonglong2 a67 = *(const ulonglong2*)(ad + 6);
            ulonglong2 b   = *(const ulonglong2*)&sg.Bs[buf][kk][lane << 2];
            acc[0][0]=fma2(a01.x,b.x,acc[0][0]); acc[0][1]=fma2(a01.x,b.y,acc[0][1]);
            acc[1][0]=fma2(a01.y,b.x,acc[1][0]); acc[1][1]=fma2(a01.y,b.y,acc[1][1]);
            acc[2][0]=fma2(a23.x,b.x,acc[2][0]); acc[2][1]=fma2(a23.x,b.y,acc[2][1]);
            acc[3][0]=fma2(a23.y,b.x,acc[3][0]); acc[3][1]=fma2(a23.y,b.y,acc[3][1]);
            acc[4][0]=fma2(a45.x,b.x,acc[4][0]); acc[4][1]=fma2(a45.x,b.y,acc[4][1]);
            acc[5][0]=fma2(a45.y,b.x,acc[5][0]); acc[5][1]=fma2(a45.y,b.y,acc[5][1]);
            acc[6][0]=fma2(a67.x,b.x,acc[6][0]); acc[6][1]=fma2(a67.x,b.y,acc[6][1]);
            acc[7][0]=fma2(a67.y,b.x,acc[7][0]); acc[7][1]=fma2(a67.y,b.y,acc[7][1]);
        }
        if (c + 1 < NC && tid < 128) sg.AsD[(c+1)&1][ak][ar] = pack2(aNext, aNext);
        __syncthreads();
    }
    #undef STAGE_B

    // split-K reduce: two passes through a [4][8][128] buffer aliasing Bs (16 KB)
    float* Red = (float*)&sg.Bs[0][0][0];
    if (w < 4) {
        #pragma unroll
        for (int r = 0; r < 8; r++) {
            float x0, x1, x2, x3;
            unpack2(acc[r][0], x0, x1);
            unpack2(acc[r][1], x2, x3);
            *(float4*)&Red[((w << 3) + r)*CC + (lane << 2)] = make_float4(x0, x1, x2, x3);
        }
    }
    __syncthreads();
    if (w >= 4) {
        #pragma unroll
        for (int r = 0; r < 8; r++) {
            float x0, x1, x2, x3;
            unpack2(acc[r][0], x0, x1);
            unpack2(acc[r][1], x2, x3);
            float4* p = (float4*)&Red[(((w - 4) << 3) + r)*CC + (lane << 2)];
            float4 t = *p;
            t.x += x0; t.y += x1; t.z += x2; t.w += x3;
            *p = t;
        }
    }
    __syncthreads();
    const int rr = tid >> 5, c4 = (tid & 31) << 2;
    float4 s0 = *(float4*)&Red[(rr)*CC + c4];
    float4 s1 = *(float4*)&Red[(8  + rr)*CC + c4];
    float4 s2 = *(float4*)&Red[(16 + rr)*CC + c4];
    float4 s3 = *(float4*)&Red[(24 + rr)*CC + c4];
    outv[0] = (s0.x + s1.x) + (s2.x + s3.x);
    outv[1] = (s0.y + s1.y) + (s2.y + s3.y);
    outv[2] = (s0.z + s1.z) + (s2.z + s3.z);
    outv[3] = (s0.w + s1.w) + (s2.w + s3.w);
    // no trailing sync: next gemm_sm's entry sync protects Red.
}

// ================= Kernel A: LN1 + shift + v/r/k GEMMs =================
struct __align__(16) SmemA {
    SmemGemm gem;            // 18432
    float hs[8*132];         //  4224
    float lnaux[10][CC];     //  5120
};

__global__ void __launch_bounds__(256, 1)
kernelA(const float* __restrict__ x,
        const float* __restrict__ ln1_g, const float* __restrict__ ln1_b,
        const float* __restrict__ mu,
        const float* __restrict__ Wr, const float* __restrict__ br,
        const float* __restrict__ Wk, const float* __restrict__ bk,
        const float* __restrict__ Wv, const float* __restrict__ bv) {
    __shared__ SmemA S;
    const int tid = threadIdx.x, w = tid >> 5, lane = tid & 31;
    const int bid = blockIdx.x;
    const int bb = bid >> 6;
    const int t0 = (bid & 63) << 3;
    const int bm = bid << 3;

    // LN1 + temporal shift (8 rows + halo)
    {
        float4 g4 = *(const float4*)(ln1_g + (lane << 2));
        float4 b4 = *(const float4*)(ln1_b + (lane << 2));
        for (int hr = w; hr < 10; hr += 8) {
            int t = t0 - 1 + hr;
            bool ok = (t >= 0) && (t < TT);
            float4 xv = make_float4(0.f, 0.f, 0.f, 0.f);
            if (ok) xv = *(const float4*)(x + (size_t)((bb << 9) + t)*CC + (lane << 2));
            float mean = wsum((xv.x + xv.y) + (xv.z + xv.w)) * (1.0f/CC);
            float d0 = xv.x - mean, d1 = xv.y - mean, d2 = xv.z - mean, d3 = xv.w - mean;
            float rs = rsqrtf(wsum((d0*d0 + d1*d1) + (d2*d2 + d3*d3)) * (1.0f/CC) + 1e-5f);
            int c = lane << 2;
            S.lnaux[hr][c+0] = ok ? d0*rs*g4.x + b4.x : 0.f;
            S.lnaux[hr][c+1] = ok ? d1*rs*g4.y + b4.y : 0.f;
            S.lnaux[hr][c+2] = ok ? d2*rs*g4.z + b4.z : 0.f;
            S.lnaux[hr][c+3] = ok ? d3*rs*g4.w + b4.w : 0.f;
        }
        __syncthreads();
        for (int i = tid; i < 8*CC; i += 256) {
            int rl = i >> 7, c = i & (CC-1);
            float val = S.lnaux[rl+1][c];
            float shv = (c < CC/2) ? S.lnaux[rl][c] : S.lnaux[rl+2][c];
            S.hs[rl*132 + c] = val + mu[c]*shv;
        }
    }

    float ov[4];
    // V
    gemm_sm<CC>(S.gem, S.hs, 132, Wv, CC, 0, ov);
    {
        float4 b4 = *(const float4*)(bv + (lane << 2));
        *(float4*)(g_v + (size_t)(bm + w)*CC + (lane << 2)) =
            make_float4(ov[0]+b4.x, ov[1]+b4.y, ov[2]+b4.z, ov[3]+b4.w);
    }
    // R (sigmoid)
    gemm_sm<CC>(S.gem, S.hs, 132, Wr, CC, 0, ov);
    {
        float4 b4 = *(const float4*)(br + (lane << 2));
        float v0 = ov[0]+b4.x, v1 = ov[1]+b4.y, v2 = ov[2]+b4.z, v3 = ov[3]+b4.w;
        *(float4*)(g_r + (size_t)(bm + w)*CC + (lane << 2)) =
            make_float4(1.0f/(1.0f+expf(-v0)), 1.0f/(1.0f+expf(-v1)),
                        1.0f/(1.0f+expf(-v2)), 1.0f/(1.0f+expf(-v3)));
    }
    // K
    gemm_sm<CC>(S.gem, S.hs, 132, Wk, CC, 0, ov);
    {
        float4 b4 = *(const float4*)(bk + (lane << 2));
        *(float4*)(g_k + (size_t)(bm + w)*CC + (lane << 2)) =
            make_float4(ov[0]+b4.x, ov[1]+b4.y, ov[2]+b4.z, ov[3]+b4.w);
    }
}

// ================= Kernel B: WKV + Wo/LN2 + MLP =================
struct __align__(16) SmemB {
    SmemGemm gem;            // 18432
    float mid[8*516];        // 16512
    float h2s[8*132];        //  4224
    float wks[8*132];        //  4224
    float ys [8*CC];         //  4096
};                           // = 47488 < 48K static

__global__ void __launch_bounds__(256, 1)
kernelB(const float* __restrict__ x,
        const float* __restrict__ wd,
        const float* __restrict__ Wo, const float* __restrict__ bo,
        const float* __restrict__ g2, const float* __restrict__ be2,
        const float* __restrict__ W1, const float* __restrict__ b1,
        const float* __restrict__ W2, const float* __restrict__ b2,
        float* __restrict__ out) {
    __shared__ SmemB S;
    const int tid = threadIdx.x, w = tid >> 5, lane = tid & 31;
    const int bid = blockIdx.x;
    const int bb = bid >> 6;
    const int bm = bid << 3;
    const int row = bm + w;

    // ---- WKV: warp = row; two independent l-chains (A: [0,256), B: [256,512)),
    // each even/odd split across lane halves; x_b == x_f identity -> wk = r * x_f.
    {
        const int h = lane >> 4, p = lane & 15, c0 = p << 3;
        float bv8[8], rrow[8];
        {
            float4 k0 = *(const float4*)(g_k + (size_t)row*CC + c0);
            float4 k1 = *(const float4*)(g_k + (size_t)row*CC + c0 + 4);
            float4 w0 = *(const float4*)(wd + c0);
            float4 w1 = *(const float4*)(wd + c0 + 4);
            bv8[0] = k0.x * (-expf(w0.x)); bv8[1] = k0.y * (-expf(w0.y));
            bv8[2] = k0.z * (-expf(w0.z)); bv8[3] = k0.w * (-expf(w0.w));
            bv8[4] = k1.x * (-expf(w1.x)); bv8[5] = k1.y * (-expf(w1.y));
            bv8[6] = k1.z * (-expf(w1.z)); bv8[7] = k1.w * (-expf(w1.w));
            float4 r0 = *(const float4*)(g_r + (size_t)row*CC + c0);
            float4 r1 = *(const float4*)(g_r + (size_t)row*CC + c0 + 4);
            rrow[0]=r0.x; rrow[1]=r0.y; rrow[2]=r0.z; rrow[3]=r0.w;
            rrow[4]=r1.x; rrow[5]=r1.y; rrow[6]=r1.z; rrow[7]=r1.w;
        }
        float amax = bv8[0];
        #pragma unroll
        for (int i = 1; i < 8; i++) amax = fmaxf(amax, bv8[i]);
        #pragma unroll
        for (int o = 16; o; o >>= 1) amax = fmaxf(amax, __shfl_xor_sync(0xffffffffu, amax, o));
        #pragma unroll
        for (int i = 0; i < 8; i++) bv8[i] -= amax;

        const float inv511 = 1.0f/511.0f;
        const float sA = (float)(511 - h) * inv511;   // l = h
        const float sB = (float)(255 - h) * inv511;   // l = 256 + h
        ull Ea[4], Eb[4], gstep[4];
        #pragma unroll
        for (int j = 0; j < 4; j++) {
            Ea[j]    = pack2(expf(bv8[2*j]*sA),           expf(bv8[2*j+1]*sA));
            Eb[j]    = pack2(expf(bv8[2*j]*sB),           expf(bv8[2*j+1]*sB));
            gstep[j] = pack2(expf(-2.0f*bv8[2*j]*inv511), expf(-2.0f*bv8[2*j+1]*inv511));
        }
        ull acc2[4] = {0ull, 0ull, 0ull, 0ull};
        const float* vpA = g_v + ((size_t)(bb << 9) + h)*CC + c0;
        const float* vpB = vpA + 256*CC;

        #pragma unroll 2
        for (int i = 0; i < 128; i++) {
            ull ta = add2(add2(Ea[0], Ea[1]), add2(Ea[2], Ea[3]));
            ull tb = add2(add2(Eb[0], Eb[1]), add2(Eb[2], Eb[3]));
            float al, ah, bl, bh;
            unpack2(ta, al, ah); unpack2(tb, bl, bh);
            float za = al + ah, zb = bl + bh;
            #pragma unroll
            for (int o = 8; o; o >>= 1) {
                za += __shfl_xor_sync(0xffffffffu, za, o);
                zb += __shfl_xor_sync(0xffffffffu, zb, o);
            }
            ull invA = pack2(rcpa(za + 1e-6f), rcpa(za + 1e-6f));
            ull invB = pack2(rcpa(zb + 1e-6f), rcpa(zb + 1e-6f));
            ulonglong2 vA01 = *(const ulonglong2*)(vpA);
            ulonglong2 vA23 = *(const ulonglong2*)(vpA + 4);
            ulonglong2 vB01 = *(const ulonglong2*)(vpB);
            ulonglong2 vB23 = *(const ulonglong2*)(vpB + 4);
            acc2[0] = fma2(mul2(Ea[0], invA), vA01.x, acc2[0]);
            acc2[1] = fma2(mul2(Ea[1], invA), vA01.y, acc2[1]);
            acc2[2] = fma2(mul2(Ea[2], invA), vA23.x, acc2[2]);
            acc2[3] = fma2(mul2(Ea[3], invA), vA23.y, acc2[3]);
            acc2[0] = fma2(mul2(Eb[0], invB), vB01.x, acc2[0]);
            acc2[1] = fma2(mul2(Eb[1], invB), vB01.y, acc2[1]);
            acc2[2] = fma2(mul2(Eb[2], invB), vB23.x, acc2[2]);
            acc2[3] = fma2(mul2(Eb[3], invB), vB23.y, acc2[3]);
            Ea[0] = mul2(Ea[0], gstep[0]); Ea[1] = mul2(Ea[1], gstep[1]);
            Ea[2] = mul2(Ea[2], gstep[2]); Ea[3] = mul2(Ea[3], gstep[3]);
            Eb[0] = mul2(Eb[0], gstep[0]); Eb[1] = mul2(Eb[1], gstep[1]);
            Eb[2] = mul2(Eb[2], gstep[2]); Eb[3] = mul2(Eb[3], gstep[3]);
            vpA += 2*CC; vpB += 2*CC;
        }
        #pragma unroll
        for (int j = 0; j < 4; j++) {
            float xx, yy; unpack2(acc2[j], xx, yy);
            xx += __shfl_xor_sync(0xffffffffu, xx, 16);
            yy += __shfl_xor_sync(0xffffffffu, yy, 16);
            if (h == 0) {
                S.wks[w*132 + c0 + 2*j    ] = rrow[2*j]   * xx;
                S.wks[w*132 + c0 + 2*j + 1] = rrow[2*j+1] * yy;
            }
        }
    }

    float ov[4];
    // ---- Wo + residual + LN2
    gemm_sm<CC>(S.gem, S.wks, 132, Wo, CC, 0, ov);
    {
        float4 b4v = *(const float4*)(bo  + (lane << 2));
        float4 g4  = *(const float4*)(g2  + (lane << 2));
        float4 b4  = *(const float4*)(be2 + (lane << 2));
        float4 xv  = *(const float4*)(x + (size_t)row*CC + (lane << 2));
        float y0 = ov[0] + b4v.x + xv.x;
        float y1 = ov[1] + b4v.y + xv.y;
        float y2 = ov[2] + b4v.z + xv.z;
        float y3 = ov[3] + b4v.w + xv.w;
        *(float4*)&S.ys[w*CC + (lane << 2)] = make_float4(y0, y1, y2, y3);
        float mean = wsum((y0 + y1) + (y2 + y3)) * (1.0f/CC);
        float d0 = y0 - mean, d1 = y1 - mean, d2 = y2 - mean, d3 = y3 - mean;
        float rs = rsqrtf(wsum((d0*d0 + d1*d1) + (d2*d2 + d3*d3)) * (1.0f/CC) + 1e-5f);
        S.h2s[w*132 + (lane << 2) + 0] = d0*rs*g4.x + b4.x;
        S.h2s[w*132 + (lane << 2) + 1] = d1*rs*g4.y + b4.y;
        S.h2s[w*132 + (lane << 2) + 2] = d2*rs*g4.z + b4.z;
        S.h2s[w*132 + (lane << 2) + 3] = d3*rs*g4.w + b4.w;
    }

    // ---- W1 + exact gelu (4 n-tiles into smem mid)
    #pragma unroll 1
    for (int nb = 0; nb < 4; nb++) {
        gemm_sm<CC>(S.gem, S.h2s, 132, W1, HH, nb << 7, ov);
        float4 b4v = *(const float4*)(b1 + (nb << 7) + (lane << 2));
        float v0 = ov[0]+b4v.x, v1 = ov[1]+b4v.y, v2 = ov[2]+b4v.z, v3 = ov[3]+b4v.w;
        const float s = 0.70710678118654752f;
        v0 = 0.5f*v0*(1.0f + erff(v0*s));
        v1 = 0.5f*v1*(1.0f + erff(v1*s));
        v2 = 0.5f*v2*(1.0f + erff(v2*s));
        v3 = 0.5f*v3*(1.0f + erff(v3*s));
        *(float4*)&S.mid[w*516 + (nb << 7) + (lane << 2)] = make_float4(v0, v1, v2, v3);
    }

    // ---- W2 + residual -> out
    gemm_sm<HH>(S.gem, S.mid, 516, W2, CC, 0, ov);
    {
        float4 b4v = *(const float4*)(b2 + (lane << 2));
        float4 yv  = *(float4*)&S.ys[w*CC + (lane << 2)];
        *(float4*)(out + (size_t)row*CC + (lane << 2)) =
            make_float4(ov[0] + b4v.x + yv.x, ov[1] + b4v.y + yv.y,
                        ov[2] + b4v.z + yv.z, ov[3] + b4v.w + yv.w);
    }
}

// ---------------- launch ----------------
extern "C" void kernel_launch(void* const* d_in, const int* in_sizes, int n_in,
                              void* d_out, int out_size) {
    const float* x       = (const float*)d_in[0];
    const float* ln1_g   = (const float*)d_in[1];
    const float* ln1_b   = (const float*)d_in[2];
    const float* mu      = (const float*)d_in[3];
    const float* Wr      = (const float*)d_in[4];
    const float* br      = (const float*)d_in[5];
    const float* Wk      = (const float*)d_in[6];
    const float* bk      = (const float*)d_in[7];
    const float* Wv      = (const float*)d_in[8];
    const float* bv      = (const float*)d_in[9];
    const float* w_decay = (const float*)d_in[10];
    const float* Wo      = (const float*)d_in[11];
    const float* bo      = (const float*)d_in[12];
    const float* ln2_g   = (const float*)d_in[13];
    const float* ln2_b   = (const float*)d_in[14];
    const float* W1      = (const float*)d_in[15];
    const float* b1      = (const float*)d_in[16];
    const float* W2      = (const float*)d_in[17];
    const float* b2      = (const float*)d_in[18];
    float* out = (float*)d_out;

    kernelA<<<128, 256>>>(x, ln1_g, ln1_b, mu, Wr, br, Wk, bk, Wv, bv);
    kernelB<<<128, 256>>>(x, w_decay, Wo, bo, ln2_g, ln2_b, W1, b1, W2, b2, out);
}